// round 16
// baseline (speedup 1.0000x reference)
#include <cuda_runtime.h>
#include <cuda_bf16.h>

typedef unsigned long long u64;

constexpr int B = 4096, T = 200, F = 36;
constexpr int THREADS = 256, WARPS = 8, NBW = 4;   // 4 batches per warp
constexpr int BPB  = WARPS * NBW;                  // 32
constexpr int GRID = B / BPB;                      // 128

// Weight layout (floats). Per lane-block: 4 rows (=2 pairs), element-interleaved
// so one LDS.128 = 2 cols x 2 rows feeds 2 FFMA2. +4 skew per lane block.
constexpr int W1_STRIDE = 212, W2_STRIDE = 196, W3_STRIDE = 196;
constexpr int W1_WHOFF  = 144, W2_WHOFF  = 64,  W3_WHOFF  = 128;
constexpr int OFF_W1 = 0;
constexpr int OFF_W2 = OFF_W1 + 16 * W1_STRIDE;
constexpr int OFF_W3 = OFF_W2 + 32 * W2_STRIDE;
constexpr int OFF_B2 = OFF_W3 + 16 * W3_STRIDE;
constexpr int OFF_B3 = OFF_B2 + 128;
constexpr int OFF_H  = OFF_B3 + 64;

// Per-warp h region (u64 = duplicated f32x2). Padded strides for bank spread.
constexpr int H1_STR = 18, H2_STR = 34, H3_STR = 18;
constexpr int HW_H1 = 0, HW_H2 = 4 * H1_STR, HW_H3 = HW_H2 + 4 * H2_STR;
constexpr int HW_TOTAL = HW_H3 + 4 * H3_STR;
constexpr int SMEM_FLOATS = OFF_H + WARPS * HW_TOTAL * 2;
constexpr int SMEM_BYTES  = SMEM_FLOATS * 4;

__device__ float g_Wc[6 * 16];
__device__ float g_bc[6];
// pre1[b][t][un(16)][pair(2)] u64 = {preA,preB}; pair0={i,f}, pair1={g,o}; biases folded.
__device__ u64 g_pre1[(size_t)B * T * 32];

__device__ __forceinline__ void fma2(u64 &acc, u64 w, u64 x) {
    asm("fma.rn.f32x2 %0, %1, %2, %0;" : "+l"(acc) : "l"(w), "l"(x));
}
__device__ __forceinline__ void add2(u64 &acc, u64 a, u64 b) {
    asm("add.rn.f32x2 %0, %1, %2;" : "=l"(acc) : "l"(a), "l"(b));
}
__device__ __forceinline__ u64 pk(float v) {
    u64 r; asm("mov.b64 %0, {%1, %1};" : "=l"(r) : "f"(v)); return r;
}
__device__ __forceinline__ u64 pkp(float lo, float hi) {
    u64 r; asm("mov.b64 %0, {%1, %2};" : "=l"(r) : "f"(lo), "f"(hi)); return r;
}
__device__ __forceinline__ void upk(u64 v, float &lo, float &hi) {
    asm("mov.b64 {%0, %1}, %2;" : "=f"(lo), "=f"(hi) : "l"(v));
}
__device__ __forceinline__ float sigf(float x) {
    return __fdividef(1.0f, 1.0f + __expf(-x));
}
__device__ __forceinline__ float tanh_(float x) {
    return __fdividef(2.0f, 1.0f + __expf(-2.0f * x)) - 1.0f;
}

__global__ void __launch_bounds__(THREADS, 1) lstm_fused(
    const float* __restrict__ Whh1,
    const float* __restrict__ Wih2, const float* __restrict__ Whh2,
    const float* __restrict__ bih2, const float* __restrict__ bhh2,
    const float* __restrict__ Wih3, const float* __restrict__ Whh3,
    const float* __restrict__ bih3, const float* __restrict__ bhh3,
    float* __restrict__ out)
{
    extern __shared__ float sm[];
    const int tid = threadIdx.x;

    // ---- stage weights into skewed interleaved layout ----
    for (int idx = tid; idx < 64 * 16; idx += THREADS) {
        int r = idx >> 4, j = idx & 15;
        int q = r >> 4, un = r & 15, p = q >> 1, s = q & 1;
        sm[OFF_W1 + un * W1_STRIDE + W1_WHOFF + p * 32 + 2 * j + s] = Whh1[idx];
    }
    for (int idx = tid; idx < 128 * 16; idx += THREADS) {
        int r = idx >> 4, j = idx & 15;
        int q = r >> 5, un = r & 31, p = q >> 1, s = q & 1;
        sm[OFF_W2 + un * W2_STRIDE + p * 32 + 2 * j + s] = Wih2[idx];
    }
    for (int idx = tid; idx < 128 * 32; idx += THREADS) {
        int r = idx >> 5, j = idx & 31;
        int q = r >> 5, un = r & 31, p = q >> 1, s = q & 1;
        sm[OFF_W2 + un * W2_STRIDE + W2_WHOFF + p * 64 + 2 * j + s] = Whh2[idx];
    }
    for (int r = tid; r < 128; r += THREADS) {
        int q = r >> 5, un = r & 31, p = q >> 1, s = q & 1;
        sm[OFF_B2 + (un * 2 + p) * 2 + s] = bih2[r] + bhh2[r];
    }
    for (int idx = tid; idx < 64 * 32; idx += THREADS) {
        int r = idx >> 5, j = idx & 31;
        int q = r >> 4, un = r & 15, p = q >> 1, s = q & 1;
        sm[OFF_W3 + un * W3_STRIDE + p * 64 + 2 * j + s] = Wih3[idx];
    }
    for (int idx = tid; idx < 64 * 16; idx += THREADS) {
        int r = idx >> 4, j = idx & 15;
        int q = r >> 4, un = r & 15, p = q >> 1, s = q & 1;
        sm[OFF_W3 + un * W3_STRIDE + W3_WHOFF + p * 32 + 2 * j + s] = Whh3[idx];
    }
    for (int r = tid; r < 64; r += THREADS) {
        int q = r >> 4, un = r & 15, p = q >> 1, s = q & 1;
        sm[OFF_B3 + (un * 2 + p) * 2 + s] = bih3[r] + bhh3[r];
    }
    for (int i = tid; i < WARPS * HW_TOTAL * 2; i += THREADS)
        sm[OFF_H + i] = 0.0f;
    __syncthreads();

    const int lane = tid & 31;
    const int w    = tid >> 5;
    const int half = lane >> 4;
    const int hl   = lane & 15;

    u64* hw  = reinterpret_cast<u64*>(sm + OFF_H) + w * HW_TOTAL;
    u64* h1u = hw + HW_H1;
    u64* h2u = hw + HW_H2;
    u64* h3u = hw + HW_H3;

    const float* w1 = sm + OFF_W1 + hl * W1_STRIDE;
    const float* w2 = sm + OFF_W2 + lane * W2_STRIDE;
    const float* w3 = sm + OFF_W3 + hl * W3_STRIDE;
    const u64* b2 = reinterpret_cast<const u64*>(sm + OFF_B2) + lane * 2;
    const u64* b3 = reinterpret_cast<const u64*>(sm + OFF_B3) + hl * 2;

    // L2 input-projection weights -> registers (32 u64, loaded once):
    // deletes 16 distinct-address LDS.128 (4 wf each) per warp per step.
    u64 w2xr[32];
    #pragma unroll
    for (int k = 0; k < 32; k++)
        w2xr[k] = *reinterpret_cast<const u64*>(w2 + 2 * k);

    // L3 recurrent weights -> registers (32 u64 covers all 16 cols x 2 pairs)
    u64 wh3r[32];
    #pragma unroll
    for (int p = 0; p < 2; p++)
        #pragma unroll
        for (int j = 0; j < 16; j++)
            wh3r[p * 16 + j] = *reinterpret_cast<const u64*>(w3 + W3_WHOFF + p * 32 + 2 * j);

    const int b0 = blockIdx.x * BPB + w * NBW;
    const int bA = b0 + half * 2 + 0;
    const int bB = b0 + half * 2 + 1;

    const ulonglong2* preA = reinterpret_cast<const ulonglong2*>(g_pre1) + (size_t)bA * T * 16 + hl;
    const ulonglong2* preB = reinterpret_cast<const ulonglong2*>(g_pre1) + (size_t)bB * T * 16 + hl;

    const u64* h1self = h1u + half * 2 * H1_STR;
    const u64* h2self = h2u + half * 2 * H2_STR;
    const u64* h3self = h3u + half * 2 * H3_STR;

    float c1[2] = {0.f, 0.f}, c3[2] = {0.f, 0.f};
    float c2[4] = {0.f, 0.f, 0.f, 0.f};

    ulonglong2 pc0 = __ldg(preA);
    ulonglong2 pc1 = __ldg(preB);

    for (int t = 0; t < T; t++) {
        ulonglong2 pn0, pn1;
        if (t < T - 1) {
            pn0 = __ldg(preA + (size_t)(t + 1) * 16);
            pn1 = __ldg(preB + (size_t)(t + 1) * 16);
        }

        // ================= Layer 1 =================
        u64 a1[2][2];
        a1[0][0] = pc0.x; a1[0][1] = pc0.y;
        a1[1][0] = pc1.x; a1[1][1] = pc1.y;
        #pragma unroll
        for (int j = 0; j < 16; j += 2) {
            ulonglong2 hx0 = *reinterpret_cast<const ulonglong2*>(h1self + 0 * H1_STR + j);
            ulonglong2 hx1 = *reinterpret_cast<const ulonglong2*>(h1self + 1 * H1_STR + j);
            #pragma unroll
            for (int p = 0; p < 2; p++) {
                ulonglong2 wv = *reinterpret_cast<const ulonglong2*>(w1 + W1_WHOFF + p * 32 + 2 * j);
                fma2(a1[0][p], wv.x, hx0.x); fma2(a1[0][p], wv.y, hx0.y);
                fma2(a1[1][p], wv.x, hx1.x); fma2(a1[1][p], wv.y, hx1.y);
            }
        }
        #pragma unroll
        for (int ln = 0; ln < 2; ln++) {
            float gi, gf, gg, go;
            upk(a1[ln][0], gi, gf);
            upk(a1[ln][1], gg, go);
            float cc = fmaf(sigf(gf), c1[ln], sigf(gi) * tanh_(gg));
            c1[ln] = cc;
            h1u[(half * 2 + ln) * H1_STR + hl] = pk(sigf(go) * tanh_(cc));
        }
        __syncwarp();

        // ================= Layer 2 =================
        u64 a2[4][2];
        #pragma unroll
        for (int n = 0; n < 4; n++) { a2[n][0] = b2[0]; a2[n][1] = b2[1]; }
        #pragma unroll
        for (int j = 0; j < 16; j += 2) {
            #pragma unroll
            for (int n = 0; n < 4; n++) {
                ulonglong2 hx = *reinterpret_cast<const ulonglong2*>(h1u + n * H1_STR + j);
                fma2(a2[n][0], w2xr[j],     hx.x);  fma2(a2[n][0], w2xr[j + 1],  hx.y);
                fma2(a2[n][1], w2xr[16 + j], hx.x); fma2(a2[n][1], w2xr[17 + j], hx.y);
            }
        }
        #pragma unroll
        for (int j = 0; j < 32; j += 2) {
            ulonglong2 w0 = *reinterpret_cast<const ulonglong2*>(w2 + W2_WHOFF + 2 * j);
            ulonglong2 w1v = *reinterpret_cast<const ulonglong2*>(w2 + W2_WHOFF + 64 + 2 * j);
            #pragma unroll
            for (int n = 0; n < 4; n++) {
                ulonglong2 hx = *reinterpret_cast<const ulonglong2*>(h2u + n * H2_STR + j);
                fma2(a2[n][0], w0.x, hx.x);  fma2(a2[n][0], w0.y, hx.y);
                fma2(a2[n][1], w1v.x, hx.x); fma2(a2[n][1], w1v.y, hx.y);
            }
        }
        #pragma unroll
        for (int n = 0; n < 4; n++) {
            float gi, gf, gg, go;
            upk(a2[n][0], gi, gf);
            upk(a2[n][1], gg, go);
            float cc = fmaf(sigf(gf), c2[n], sigf(gi) * tanh_(gg));
            c2[n] = cc;
            h2u[n * H2_STR + lane] = pk(sigf(go) * tanh_(cc));
        }
        __syncwarp();

        // ================= Layer 3 =================
        u64 a3[2][2];
        a3[0][0] = b3[0]; a3[0][1] = b3[1];
        a3[1][0] = b3[0]; a3[1][1] = b3[1];
        #pragma unroll
        for (int j = 0; j < 32; j += 2) {
            ulonglong2 hx0 = *reinterpret_cast<const ulonglong2*>(h2self + 0 * H2_STR + j);
            ulonglong2 hx1 = *reinterpret_cast<const ulonglong2*>(h2self + 1 * H2_STR + j);
            #pragma unroll
            for (int p = 0; p < 2; p++) {
                ulonglong2 wv = *reinterpret_cast<const ulonglong2*>(w3 + p * 64 + 2 * j);
                fma2(a3[0][p], wv.x, hx0.x); fma2(a3[0][p], wv.y, hx0.y);
                fma2(a3[1][p], wv.x, hx1.x); fma2(a3[1][p], wv.y, hx1.y);
            }
        }
        #pragma unroll
        for (int j = 0; j < 16; j += 2) {
            ulonglong2 hx0 = *reinterpret_cast<const ulonglong2*>(h3self + 0 * H3_STR + j);
            ulonglong2 hx1 = *reinterpret_cast<const ulonglong2*>(h3self + 1 * H3_STR + j);
            #pragma unroll
            for (int p = 0; p < 2; p++) {
                fma2(a3[0][p], wh3r[p * 16 + j],     hx0.x);
                fma2(a3[0][p], wh3r[p * 16 + j + 1], hx0.y);
                fma2(a3[1][p], wh3r[p * 16 + j],     hx1.x);
                fma2(a3[1][p], wh3r[p * 16 + j + 1], hx1.y);
            }
        }
        #pragma unroll
        for (int ln = 0; ln < 2; ln++) {
            float gi, gf, gg, go;
            upk(a3[ln][0], gi, gf);
            upk(a3[ln][1], gg, go);
            float cc = fmaf(sigf(gf), c3[ln], sigf(gi) * tanh_(gg));
            c3[ln] = cc;
            h3u[(half * 2 + ln) * H3_STR + hl] = pk(sigf(go) * tanh_(cc));
        }
        __syncwarp();

        pc0 = pn0; pc1 = pn1;
    }

    if (lane < 24) {
        int n = lane / 6, cls = lane - n * 6;
        const float* hrow = reinterpret_cast<const float*>(h3u + n * H3_STR);
        float acc = g_bc[cls];
        #pragma unroll
        for (int u = 0; u < 16; u++)
            acc = fmaf(hrow[2 * u], g_Wc[cls * 16 + u], acc);
        out[(size_t)(b0 + n) * 6 + cls] = acc;
    }
}

// ---- pre1 v4: SMEM-staged tiles storing PLAIN floats (not duplicated).
// Halves the staging STS bytes and the compute-side LDS count (9 broadcast
// LDS.128 per bt row instead of 18); per-lane pk duplication moves to the
// underutilized ALU pipe. 296 blocks = one balanced wave at 2 blocks/SM.
constexpr int P1_THREADS = 256;
constexpr int P1_TILE    = 64;
constexpr int P1_GRID    = 296;
constexpr int P1_NTILES  = (B * T) / P1_TILE;   // 12800

__global__ void __launch_bounds__(P1_THREADS) pre1_kernel(
    const float* __restrict__ x,
    const float* __restrict__ Wih1,
    const float* __restrict__ bih1, const float* __restrict__ bhh1)
{
    __shared__ float xs[2][P1_TILE * F];   // 2 x 9216 B

    const int tid  = threadIdx.x;
    const int lane = tid & 31;
    const int w    = tid >> 5;
    const int un = lane >> 1, pr = lane & 1;
    const int rA = pr * 32 + un;     // pr=0: (i_un, f_un)   pr=1: (g_un, o_un)
    const int rB = rA + 16;

    u64 wp[F];
    #pragma unroll
    for (int j = 0; j < F; j++)
        wp[j] = pkp(__ldg(Wih1 + rA * F + j), __ldg(Wih1 + rB * F + j));
    const u64 bias = pkp(bih1[rA] + bhh1[rA], bih1[rB] + bhh1[rB]);

    int tile = blockIdx.x;
    if (tile < P1_NTILES) {
        const float* src = x + (size_t)tile * P1_TILE * F;
        #pragma unroll
        for (int r = 0; r < 9; r++)
            xs[0][tid + r * P1_THREADS] = __ldg(src + tid + r * P1_THREADS);
    }
    __syncthreads();

    int buf = 0;
    for (; tile < P1_NTILES; tile += P1_GRID) {
        const int ntile = tile + P1_GRID;
        float nv[9];
        if (ntile < P1_NTILES) {
            const float* src = x + (size_t)ntile * P1_TILE * F;
            #pragma unroll
            for (int r = 0; r < 9; r++)
                nv[r] = __ldg(src + tid + r * P1_THREADS);
        }

        // compute: this warp's 8 bt rows of the tile
        const float* xw = xs[buf] + w * 8 * F;
        u64* dst = g_pre1 + (size_t)tile * P1_TILE * 32 + (size_t)w * 8 * 32 + lane;
        #pragma unroll
        for (int n = 0; n < 8; n++) {
            // row base = n*144 B -> 16B-aligned, broadcast float4 LDS
            const float4* xr = reinterpret_cast<const float4*>(xw + n * F);
            u64 a0 = bias, a1 = 0ull, a2 = 0ull, a3 = 0ull;
            #pragma unroll
            for (int q = 0; q < 9; q++) {
                float4 xv = xr[q];
                fma2(a0, wp[4 * q + 0], pk(xv.x));
                fma2(a1, wp[4 * q + 1], pk(xv.y));
                fma2(a2, wp[4 * q + 2], pk(xv.z));
                fma2(a3, wp[4 * q + 3], pk(xv.w));
            }
            u64 s0, s1, acc;
            add2(s0, a0, a1);
            add2(s1, a2, a3);
            add2(acc, s0, s1);
            dst[n * 32] = acc;
        }

        if (ntile < P1_NTILES) {
            #pragma unroll
            for (int r = 0; r < 9; r++)
                xs[buf ^ 1][tid + r * P1_THREADS] = nv[r];
        }
        buf ^= 1;
        __syncthreads();
    }
}

// Collapse the 3 linear head layers into Wc [6,16], bc [6].
__global__ void head_precompute(
    const float* __restrict__ Wfc1, const float* __restrict__ bfc1,
    const float* __restrict__ Wfc2, const float* __restrict__ bfc2,
    const float* __restrict__ Wcls, const float* __restrict__ bcls)
{
    __shared__ float tmp[6 * 128];
    const int tid = threadIdx.x;

    for (int idx = tid; idx < 6 * 128; idx += blockDim.x) {
        int j = idx / 128, p = idx % 128;
        float s = 0.0f;
        for (int q = 0; q < 32; q++)
            s += Wcls[j * 32 + q] * Wfc2[q * 128 + p];
        tmp[idx] = s;
    }
    __syncthreads();

    for (int idx = tid; idx < 6 * 16; idx += blockDim.x) {
        int j = idx / 16, u = idx % 16;
        float s = 0.0f;
        for (int p = 0; p < 128; p++)
            s += tmp[j * 128 + p] * Wfc1[p * 16 + u];
        g_Wc[idx] = s;
    }
    if (tid < 6) {
        float s = bcls[tid];
        for (int q = 0; q < 32; q++)
            s += Wcls[tid * 32 + q] * bfc2[q];
        for (int p = 0; p < 128; p++)
            s += tmp[tid * 128 + p] * bfc1[p];
        g_bc[tid] = s;
    }
}

extern "C" void kernel_launch(void* const* d_in, const int* in_sizes, int n_in,
                              void* d_out, int out_size)
{
    (void)in_sizes; (void)n_in; (void)out_size;
    const float* x    = (const float*)d_in[0];
    const float* Wih1 = (const float*)d_in[1];
    const float* Whh1 = (const float*)d_in[2];
    const float* bih1 = (const float*)d_in[3];
    const float* bhh1 = (const float*)d_in[4];
    const float* Wih2 = (const float*)d_in[5];
    const float* Whh2 = (const float*)d_in[6];
    const float* bih2 = (const float*)d_in[7];
    const float* bhh2 = (const float*)d_in[8];
    const float* Wih3 = (const float*)d_in[9];
    const float* Whh3 = (const float*)d_in[10];
    const float* bih3 = (const float*)d_in[11];
    const float* bhh3 = (const float*)d_in[12];
    const float* Wfc1 = (const float*)d_in[13];
    const float* bfc1 = (const float*)d_in[14];
    const float* Wfc2 = (const float*)d_in[15];
    const float* bfc2 = (const float*)d_in[16];
    const float* Wcls = (const float*)d_in[17];
    const float* bcls = (const float*)d_in[18];
    float* out = (float*)d_out;

    static bool attr_set = false;
    if (!attr_set) {
        cudaFuncSetAttribute(lstm_fused,
                             cudaFuncAttributeMaxDynamicSharedMemorySize,
                             SMEM_BYTES);
        attr_set = true;
    }

    pre1_kernel<<<P1_GRID, P1_THREADS>>>(x, Wih1, bih1, bhh1);
    head_precompute<<<1, 256>>>(Wfc1, bfc1, Wfc2, bfc2, Wcls, bcls);
    lstm_fused<<<GRID, THREADS, SMEM_BYTES>>>(
        Whh1, Wih2, Whh2, bih2, bhh2,
        Wih3, Whh3, bih3, bhh3, out);
}

// round 17
// speedup vs baseline: 1.0592x; 1.0592x over previous
#include <cuda_runtime.h>
#include <cuda_bf16.h>

typedef unsigned long long u64;

constexpr int B = 4096, T = 200, F = 36;
constexpr int THREADS = 256, WARPS = 8, NBW = 4;   // 4 batches per warp
constexpr int BPB  = WARPS * NBW;                  // 32
constexpr int GRID = B / BPB;                      // 128

// Weight layout (floats). Per lane-block: 4 rows (=2 pairs), element-interleaved
// so one LDS.128 = 2 cols x 2 rows feeds 2 FFMA2. +4 skew per lane block.
constexpr int W1_STRIDE = 212, W2_STRIDE = 196, W3_STRIDE = 196;
constexpr int W1_WHOFF  = 144, W2_WHOFF  = 64,  W3_WHOFF  = 128;
constexpr int OFF_W1 = 0;
constexpr int OFF_W2 = OFF_W1 + 16 * W1_STRIDE;
constexpr int OFF_W3 = OFF_W2 + 32 * W2_STRIDE;
constexpr int OFF_B2 = OFF_W3 + 16 * W3_STRIDE;
constexpr int OFF_B3 = OFF_B2 + 128;
constexpr int OFF_H  = OFF_B3 + 64;

// Per-warp h region (u64 = duplicated f32x2). Padded strides for bank spread.
constexpr int H1_STR = 18, H2_STR = 34, H3_STR = 18;
constexpr int HW_H1 = 0, HW_H2 = 4 * H1_STR, HW_H3 = HW_H2 + 4 * H2_STR;
constexpr int HW_TOTAL = HW_H3 + 4 * H3_STR;
constexpr int SMEM_FLOATS = OFF_H + WARPS * HW_TOTAL * 2;
constexpr int SMEM_BYTES  = SMEM_FLOATS * 4;

__device__ float g_Wc[6 * 16];
__device__ float g_bc[6];
// pre1[b][t][un(16)][pair(2)] u64 = {preA,preB}; pair0={i,f}, pair1={g,o}; biases folded.
__device__ u64 g_pre1[(size_t)B * T * 32];

__device__ __forceinline__ void fma2(u64 &acc, u64 w, u64 x) {
    asm("fma.rn.f32x2 %0, %1, %2, %0;" : "+l"(acc) : "l"(w), "l"(x));
}
__device__ __forceinline__ void add2(u64 &acc, u64 a, u64 b) {
    asm("add.rn.f32x2 %0, %1, %2;" : "=l"(acc) : "l"(a), "l"(b));
}
__device__ __forceinline__ u64 pk(float v) {
    u64 r; asm("mov.b64 %0, {%1, %1};" : "=l"(r) : "f"(v)); return r;
}
__device__ __forceinline__ u64 pkp(float lo, float hi) {
    u64 r; asm("mov.b64 %0, {%1, %2};" : "=l"(r) : "f"(lo), "f"(hi)); return r;
}
__device__ __forceinline__ void upk(u64 v, float &lo, float &hi) {
    asm("mov.b64 {%0, %1}, %2;" : "=f"(lo), "=f"(hi) : "l"(v));
}
__device__ __forceinline__ float sigf(float x) {
    return __fdividef(1.0f, 1.0f + __expf(-x));
}
__device__ __forceinline__ float tanh_(float x) {
    return __fdividef(2.0f, 1.0f + __expf(-2.0f * x)) - 1.0f;
}

__global__ void __launch_bounds__(THREADS, 1) lstm_fused(
    const float* __restrict__ Whh1,
    const float* __restrict__ Wih2, const float* __restrict__ Whh2,
    const float* __restrict__ bih2, const float* __restrict__ bhh2,
    const float* __restrict__ Wih3, const float* __restrict__ Whh3,
    const float* __restrict__ bih3, const float* __restrict__ bhh3,
    float* __restrict__ out)
{
    extern __shared__ float sm[];
    const int tid = threadIdx.x;

    // ---- stage weights into skewed interleaved layout ----
    for (int idx = tid; idx < 64 * 16; idx += THREADS) {
        int r = idx >> 4, j = idx & 15;
        int q = r >> 4, un = r & 15, p = q >> 1, s = q & 1;
        sm[OFF_W1 + un * W1_STRIDE + W1_WHOFF + p * 32 + 2 * j + s] = Whh1[idx];
    }
    for (int idx = tid; idx < 128 * 16; idx += THREADS) {
        int r = idx >> 4, j = idx & 15;
        int q = r >> 5, un = r & 31, p = q >> 1, s = q & 1;
        sm[OFF_W2 + un * W2_STRIDE + p * 32 + 2 * j + s] = Wih2[idx];
    }
    for (int idx = tid; idx < 128 * 32; idx += THREADS) {
        int r = idx >> 5, j = idx & 31;
        int q = r >> 5, un = r & 31, p = q >> 1, s = q & 1;
        sm[OFF_W2 + un * W2_STRIDE + W2_WHOFF + p * 64 + 2 * j + s] = Whh2[idx];
    }
    for (int r = tid; r < 128; r += THREADS) {
        int q = r >> 5, un = r & 31, p = q >> 1, s = q & 1;
        sm[OFF_B2 + (un * 2 + p) * 2 + s] = bih2[r] + bhh2[r];
    }
    for (int idx = tid; idx < 64 * 32; idx += THREADS) {
        int r = idx >> 5, j = idx & 31;
        int q = r >> 4, un = r & 15, p = q >> 1, s = q & 1;
        sm[OFF_W3 + un * W3_STRIDE + p * 64 + 2 * j + s] = Wih3[idx];
    }
    for (int idx = tid; idx < 64 * 16; idx += THREADS) {
        int r = idx >> 4, j = idx & 15;
        int q = r >> 4, un = r & 15, p = q >> 1, s = q & 1;
        sm[OFF_W3 + un * W3_STRIDE + W3_WHOFF + p * 32 + 2 * j + s] = Whh3[idx];
    }
    for (int r = tid; r < 64; r += THREADS) {
        int q = r >> 4, un = r & 15, p = q >> 1, s = q & 1;
        sm[OFF_B3 + (un * 2 + p) * 2 + s] = bih3[r] + bhh3[r];
    }
    for (int i = tid; i < WARPS * HW_TOTAL * 2; i += THREADS)
        sm[OFF_H + i] = 0.0f;
    __syncthreads();

    const int lane = tid & 31;
    const int w    = tid >> 5;
    const int half = lane >> 4;
    const int hl   = lane & 15;

    u64* hw  = reinterpret_cast<u64*>(sm + OFF_H) + w * HW_TOTAL;
    u64* h1u = hw + HW_H1;
    u64* h2u = hw + HW_H2;
    u64* h3u = hw + HW_H3;

    const float* w1 = sm + OFF_W1 + hl * W1_STRIDE;
    const float* w2 = sm + OFF_W2 + lane * W2_STRIDE;
    const float* w3 = sm + OFF_W3 + hl * W3_STRIDE;
    const u64* b2 = reinterpret_cast<const u64*>(sm + OFF_B2) + lane * 2;
    const u64* b3 = reinterpret_cast<const u64*>(sm + OFF_B3) + hl * 2;

    // L2 input-projection weights -> registers (32 u64, loaded once):
    // deletes 16 distinct-address LDS.128 (4 wf each) per warp per step.
    u64 w2xr[32];
    #pragma unroll
    for (int k = 0; k < 32; k++)
        w2xr[k] = *reinterpret_cast<const u64*>(w2 + 2 * k);

    // L3 recurrent weights -> registers (32 u64 covers all 16 cols x 2 pairs)
    u64 wh3r[32];
    #pragma unroll
    for (int p = 0; p < 2; p++)
        #pragma unroll
        for (int j = 0; j < 16; j++)
            wh3r[p * 16 + j] = *reinterpret_cast<const u64*>(w3 + W3_WHOFF + p * 32 + 2 * j);

    const int b0 = blockIdx.x * BPB + w * NBW;
    const int bA = b0 + half * 2 + 0;
    const int bB = b0 + half * 2 + 1;

    const ulonglong2* preA = reinterpret_cast<const ulonglong2*>(g_pre1) + (size_t)bA * T * 16 + hl;
    const ulonglong2* preB = reinterpret_cast<const ulonglong2*>(g_pre1) + (size_t)bB * T * 16 + hl;

    const u64* h1self = h1u + half * 2 * H1_STR;
    const u64* h2self = h2u + half * 2 * H2_STR;
    const u64* h3self = h3u + half * 2 * H3_STR;

    float c1[2] = {0.f, 0.f}, c3[2] = {0.f, 0.f};
    float c2[4] = {0.f, 0.f, 0.f, 0.f};

    ulonglong2 pc0 = __ldg(preA);
    ulonglong2 pc1 = __ldg(preB);

    for (int t = 0; t < T; t++) {
        ulonglong2 pn0, pn1;
        if (t < T - 1) {
            pn0 = __ldg(preA + (size_t)(t + 1) * 16);
            pn1 = __ldg(preB + (size_t)(t + 1) * 16);
        }

        // ================= Layer 1 =================
        u64 a1[2][2];
        a1[0][0] = pc0.x; a1[0][1] = pc0.y;
        a1[1][0] = pc1.x; a1[1][1] = pc1.y;
        #pragma unroll
        for (int j = 0; j < 16; j += 2) {
            ulonglong2 hx0 = *reinterpret_cast<const ulonglong2*>(h1self + 0 * H1_STR + j);
            ulonglong2 hx1 = *reinterpret_cast<const ulonglong2*>(h1self + 1 * H1_STR + j);
            #pragma unroll
            for (int p = 0; p < 2; p++) {
                ulonglong2 wv = *reinterpret_cast<const ulonglong2*>(w1 + W1_WHOFF + p * 32 + 2 * j);
                fma2(a1[0][p], wv.x, hx0.x); fma2(a1[0][p], wv.y, hx0.y);
                fma2(a1[1][p], wv.x, hx1.x); fma2(a1[1][p], wv.y, hx1.y);
            }
        }
        #pragma unroll
        for (int ln = 0; ln < 2; ln++) {
            float gi, gf, gg, go;
            upk(a1[ln][0], gi, gf);
            upk(a1[ln][1], gg, go);
            float cc = fmaf(sigf(gf), c1[ln], sigf(gi) * tanh_(gg));
            c1[ln] = cc;
            h1u[(half * 2 + ln) * H1_STR + hl] = pk(sigf(go) * tanh_(cc));
        }
        __syncwarp();

        // ================= Layer 2 =================
        u64 a2[4][2];
        #pragma unroll
        for (int n = 0; n < 4; n++) { a2[n][0] = b2[0]; a2[n][1] = b2[1]; }
        #pragma unroll
        for (int j = 0; j < 16; j += 2) {
            #pragma unroll
            for (int n = 0; n < 4; n++) {
                ulonglong2 hx = *reinterpret_cast<const ulonglong2*>(h1u + n * H1_STR + j);
                fma2(a2[n][0], w2xr[j],     hx.x);  fma2(a2[n][0], w2xr[j + 1],  hx.y);
                fma2(a2[n][1], w2xr[16 + j], hx.x); fma2(a2[n][1], w2xr[17 + j], hx.y);
            }
        }
        #pragma unroll
        for (int j = 0; j < 32; j += 2) {
            ulonglong2 w0 = *reinterpret_cast<const ulonglong2*>(w2 + W2_WHOFF + 2 * j);
            ulonglong2 w1v = *reinterpret_cast<const ulonglong2*>(w2 + W2_WHOFF + 64 + 2 * j);
            #pragma unroll
            for (int n = 0; n < 4; n++) {
                ulonglong2 hx = *reinterpret_cast<const ulonglong2*>(h2u + n * H2_STR + j);
                fma2(a2[n][0], w0.x, hx.x);  fma2(a2[n][0], w0.y, hx.y);
                fma2(a2[n][1], w1v.x, hx.x); fma2(a2[n][1], w1v.y, hx.y);
            }
        }
        #pragma unroll
        for (int n = 0; n < 4; n++) {
            float gi, gf, gg, go;
            upk(a2[n][0], gi, gf);
            upk(a2[n][1], gg, go);
            float cc = fmaf(sigf(gf), c2[n], sigf(gi) * tanh_(gg));
            c2[n] = cc;
            h2u[n * H2_STR + lane] = pk(sigf(go) * tanh_(cc));
        }
        __syncwarp();

        // ================= Layer 3 =================
        u64 a3[2][2];
        a3[0][0] = b3[0]; a3[0][1] = b3[1];
        a3[1][0] = b3[0]; a3[1][1] = b3[1];
        #pragma unroll
        for (int j = 0; j < 32; j += 2) {
            ulonglong2 hx0 = *reinterpret_cast<const ulonglong2*>(h2self + 0 * H2_STR + j);
            ulonglong2 hx1 = *reinterpret_cast<const ulonglong2*>(h2self + 1 * H2_STR + j);
            #pragma unroll
            for (int p = 0; p < 2; p++) {
                ulonglong2 wv = *reinterpret_cast<const ulonglong2*>(w3 + p * 64 + 2 * j);
                fma2(a3[0][p], wv.x, hx0.x); fma2(a3[0][p], wv.y, hx0.y);
                fma2(a3[1][p], wv.x, hx1.x); fma2(a3[1][p], wv.y, hx1.y);
            }
        }
        #pragma unroll
        for (int j = 0; j < 16; j += 2) {
            ulonglong2 hx0 = *reinterpret_cast<const ulonglong2*>(h3self + 0 * H3_STR + j);
            ulonglong2 hx1 = *reinterpret_cast<const ulonglong2*>(h3self + 1 * H3_STR + j);
            #pragma unroll
            for (int p = 0; p < 2; p++) {
                fma2(a3[0][p], wh3r[p * 16 + j],     hx0.x);
                fma2(a3[0][p], wh3r[p * 16 + j + 1], hx0.y);
                fma2(a3[1][p], wh3r[p * 16 + j],     hx1.x);
                fma2(a3[1][p], wh3r[p * 16 + j + 1], hx1.y);
            }
        }
        #pragma unroll
        for (int ln = 0; ln < 2; ln++) {
            float gi, gf, gg, go;
            upk(a3[ln][0], gi, gf);
            upk(a3[ln][1], gg, go);
            float cc = fmaf(sigf(gf), c3[ln], sigf(gi) * tanh_(gg));
            c3[ln] = cc;
            h3u[(half * 2 + ln) * H3_STR + hl] = pk(sigf(go) * tanh_(cc));
        }
        __syncwarp();

        pc0 = pn0; pc1 = pn1;
    }

    if (lane < 24) {
        int n = lane / 6, cls = lane - n * 6;
        const float* hrow = reinterpret_cast<const float*>(h3u + n * H3_STR);
        float acc = g_bc[cls];
        #pragma unroll
        for (int u = 0; u < 16; u++)
            acc = fmaf(hrow[2 * u], g_Wc[cls * 16 + u], acc);
        out[(size_t)(b0 + n) * 6 + cls] = acc;
    }
}

// ---- pre1 v5: v4 plain-float staging + forced 2 blocks/SM.
// v4 cut L1 pipe 78.5% -> 42% but regs rose to 133 (>128) dropping to
// 1 block/SM; __launch_bounds__(256, 2) caps regs at 128 to restore
// 2 blocks/SM while keeping the halved crossbar traffic.
constexpr int P1_THREADS = 256;
constexpr int P1_TILE    = 64;
constexpr int P1_GRID    = 296;
constexpr int P1_NTILES  = (B * T) / P1_TILE;   // 12800

__global__ void __launch_bounds__(P1_THREADS, 2) pre1_kernel(
    const float* __restrict__ x,
    const float* __restrict__ Wih1,
    const float* __restrict__ bih1, const float* __restrict__ bhh1)
{
    __shared__ float xs[2][P1_TILE * F];   // 2 x 9216 B

    const int tid  = threadIdx.x;
    const int lane = tid & 31;
    const int w    = tid >> 5;
    const int un = lane >> 1, pr = lane & 1;
    const int rA = pr * 32 + un;     // pr=0: (i_un, f_un)   pr=1: (g_un, o_un)
    const int rB = rA + 16;

    u64 wp[F];
    #pragma unroll
    for (int j = 0; j < F; j++)
        wp[j] = pkp(__ldg(Wih1 + rA * F + j), __ldg(Wih1 + rB * F + j));
    const u64 bias = pkp(bih1[rA] + bhh1[rA], bih1[rB] + bhh1[rB]);

    int tile = blockIdx.x;
    if (tile < P1_NTILES) {
        const float* src = x + (size_t)tile * P1_TILE * F;
        #pragma unroll
        for (int r = 0; r < 9; r++)
            xs[0][tid + r * P1_THREADS] = __ldg(src + tid + r * P1_THREADS);
    }
    __syncthreads();

    int buf = 0;
    for (; tile < P1_NTILES; tile += P1_GRID) {
        const int ntile = tile + P1_GRID;
        float nv[9];
        if (ntile < P1_NTILES) {
            const float* src = x + (size_t)ntile * P1_TILE * F;
            #pragma unroll
            for (int r = 0; r < 9; r++)
                nv[r] = __ldg(src + tid + r * P1_THREADS);
        }

        // compute: this warp's 8 bt rows of the tile
        const float* xw = xs[buf] + w * 8 * F;
        u64* dst = g_pre1 + (size_t)tile * P1_TILE * 32 + (size_t)w * 8 * 32 + lane;
        #pragma unroll
        for (int n = 0; n < 8; n++) {
            // row base = n*144 B -> 16B-aligned, broadcast float4 LDS
            const float4* xr = reinterpret_cast<const float4*>(xw + n * F);
            u64 a0 = bias, a1 = 0ull, a2 = 0ull, a3 = 0ull;
            #pragma unroll
            for (int q = 0; q < 9; q++) {
                float4 xv = xr[q];
                fma2(a0, wp[4 * q + 0], pk(xv.x));
                fma2(a1, wp[4 * q + 1], pk(xv.y));
                fma2(a2, wp[4 * q + 2], pk(xv.z));
                fma2(a3, wp[4 * q + 3], pk(xv.w));
            }
            u64 s0, s1, acc;
            add2(s0, a0, a1);
            add2(s1, a2, a3);
            add2(acc, s0, s1);
            dst[n * 32] = acc;
        }

        if (ntile < P1_NTILES) {
            #pragma unroll
            for (int r = 0; r < 9; r++)
                xs[buf ^ 1][tid + r * P1_THREADS] = nv[r];
        }
        buf ^= 1;
        __syncthreads();
    }
}

// Collapse the 3 linear head layers into Wc [6,16], bc [6].
__global__ void head_precompute(
    const float* __restrict__ Wfc1, const float* __restrict__ bfc1,
    const float* __restrict__ Wfc2, const float* __restrict__ bfc2,
    const float* __restrict__ Wcls, const float* __restrict__ bcls)
{
    __shared__ float tmp[6 * 128];
    const int tid = threadIdx.x;

    for (int idx = tid; idx < 6 * 128; idx += blockDim.x) {
        int j = idx / 128, p = idx % 128;
        float s = 0.0f;
        for (int q = 0; q < 32; q++)
            s += Wcls[j * 32 + q] * Wfc2[q * 128 + p];
        tmp[idx] = s;
    }
    __syncthreads();

    for (int idx = tid; idx < 6 * 16; idx += blockDim.x) {
        int j = idx / 16, u = idx % 16;
        float s = 0.0f;
        for (int p = 0; p < 128; p++)
            s += tmp[j * 128 + p] * Wfc1[p * 16 + u];
        g_Wc[idx] = s;
    }
    if (tid < 6) {
        float s = bcls[tid];
        for (int q = 0; q < 32; q++)
            s += Wcls[tid * 32 + q] * bfc2[q];
        for (int p = 0; p < 128; p++)
            s += tmp[tid * 128 + p] * bfc1[p];
        g_bc[tid] = s;
    }
}

extern "C" void kernel_launch(void* const* d_in, const int* in_sizes, int n_in,
                              void* d_out, int out_size)
{
    (void)in_sizes; (void)n_in; (void)out_size;
    const float* x    = (const float*)d_in[0];
    const float* Wih1 = (const float*)d_in[1];
    const float* Whh1 = (const float*)d_in[2];
    const float* bih1 = (const float*)d_in[3];
    const float* bhh1 = (const float*)d_in[4];
    const float* Wih2 = (const float*)d_in[5];
    const float* Whh2 = (const float*)d_in[6];
    const float* bih2 = (const float*)d_in[7];
    const float* bhh2 = (const float*)d_in[8];
    const float* Wih3 = (const float*)d_in[9];
    const float* Whh3 = (const float*)d_in[10];
    const float* bih3 = (const float*)d_in[11];
    const float* bhh3 = (const float*)d_in[12];
    const float* Wfc1 = (const float*)d_in[13];
    const float* bfc1 = (const float*)d_in[14];
    const float* Wfc2 = (const float*)d_in[15];
    const float* bfc2 = (const float*)d_in[16];
    const float* Wcls = (const float*)d_in[17];
    const float* bcls = (const float*)d_in[18];
    float* out = (float*)d_out;

    static bool attr_set = false;
    if (!attr_set) {
        cudaFuncSetAttribute(lstm_fused,
                             cudaFuncAttributeMaxDynamicSharedMemorySize,
                             SMEM_BYTES);
        attr_set = true;
    }

    pre1_kernel<<<P1_GRID, P1_THREADS>>>(x, Wih1, bih1, bhh1);
    head_precompute<<<1, 256>>>(Wfc1, bfc1, Wfc2, bfc2, Wcls, bcls);
    lstm_fused<<<GRID, THREADS, SMEM_BYTES>>>(
        Whh1, Wih2, Whh2, bih2, bhh2,
        Wih3, Whh3, bih3, bhh3, out);
}